// round 1
// baseline (speedup 1.0000x reference)
#include <cuda_runtime.h>
#include <cstdint>

#define BB   32
#define NSEQ 1023
#define LL   512
#define HH   1024
#define SHD  50
#define INTN 511

// Scratch (device globals; no runtime allocation allowed)
__device__ float g_up  [(size_t)BB * NSEQ * HH];
__device__ float g_down[(size_t)BB * NSEQ * HH];
__device__ float g_prec[(size_t)BB * INTN * HH];
__device__ float g_pred[(size_t)BB * INTN * 2048];

enum { M_LEAF = 0, M_PREC, M_PRED, M_UP, M_GREV, M_DOWN };

struct P {
    const float *W1, *W2, *bias;
    int ldw, K1, K2, M, Nout;
    int node_base, node_cnt;
    const int *x, *wi, *cue, *pos;
    const float *syn, *wemb, *leafW;
};

// Generic tiled GEMM with per-row gathered A (two K-segments), per-row output
// scatter, fused additive row (precomputed cons term) + bias + optional tanh.
// Block: 256 threads, tile 128x128, BK=8, 8x8 per-thread microtile.
template<int MODE, bool DOTANH>
__global__ __launch_bounds__(256) void tree_gemm(P p) {
    __shared__ const float* sA1[128];
    __shared__ const float* sA2[128];
    __shared__ const float* sAdd[128];
    __shared__ float* sOA[128];
    __shared__ float* sOB[128];
    __shared__ float As[8][128];
    __shared__ float Bs[8][132];

    const int r0 = blockIdx.y * 128;

    for (int t = threadIdx.x; t < 128; t += 256) {
        int r = r0 + t;
        const float *a1 = nullptr, *a2 = nullptr, *ad = nullptr;
        float *oA = nullptr, *oB = nullptr;
        if (r < p.M) {
            if (MODE == M_LEAF) {
                int b = r / LL, l = r % LL;
                int w = p.wi[b * LL + l];          // = L-1+l
                int s = p.x  [b * NSEQ + w];
                int c = p.cue[b * NSEQ + w];
                a1 = p.wemb + (size_t)s * HH;                     // word_e row
                a2 = p.syn  + (size_t)p.pos[b * LL + l] * SHD;    // pos_e row
                ad = p.leafW + (size_t)(HH + c) * HH;             // one-hot cue row
                oA = g_up + ((size_t)b * NSEQ + w) * HH;
            } else if (MODE == M_PREC) {
                int b = r / INTN, i = r % INTN;
                a1 = p.syn + (size_t)p.x[b * NSEQ + i] * SHD;
                oA = g_prec + (size_t)r * HH;
            } else if (MODE == M_PRED) {
                int b = r / INTN, i = r % INTN;
                int cl = 2 * i + 1, cr = 2 * i + 2;
                int il = (cl >= LL - 1) ? p.pos[b * LL + cl - (LL - 1)] : p.x[b * NSEQ + cl];
                int ir = (cr >= LL - 1) ? p.pos[b * LL + cr - (LL - 1)] : p.x[b * NSEQ + cr];
                a1 = p.syn + (size_t)il * SHD;
                a2 = p.syn + (size_t)ir * SHD;
                oA = g_pred + (size_t)r * 2048;
                oB = oA + 1024;
            } else if (MODE == M_UP) {
                int b = r / p.node_cnt, n = p.node_base + r % p.node_cnt;
                a1 = g_up + ((size_t)b * NSEQ + 2 * n + 1) * HH;
                a2 = g_up + ((size_t)b * NSEQ + 2 * n + 2) * HH;
                ad = g_prec + ((size_t)b * INTN + n) * HH;     // includes comp_b
                oA = g_up + ((size_t)b * NSEQ + n) * HH;
            } else if (MODE == M_GREV) {
                int b = r;
                a1 = g_up + (size_t)b * NSEQ * HH;             // up[:,0]
                a2 = p.syn + (size_t)p.x[b * NSEQ] * SHD;      // syn_emb[x[:,0]]
                oA = g_down + (size_t)b * NSEQ * HH;           // down[:,0]
            } else { // M_DOWN
                int b = r / p.node_cnt, n = p.node_base + r % p.node_cnt;
                a1 = g_down + ((size_t)b * NSEQ + n) * HH;
                a2 = g_up   + ((size_t)b * NSEQ + n) * HH;
                ad = g_pred + ((size_t)b * INTN + n) * 2048;   // includes dec_b + cons
                oA = g_down + ((size_t)b * NSEQ + 2 * n + 1) * HH;
                oB = g_down + ((size_t)b * NSEQ + 2 * n + 2) * HH;
            }
        }
        sA1[t] = a1; sA2[t] = a2; sAdd[t] = ad; sOA[t] = oA; sOB[t] = oB;
    }
    __syncthreads();

    float acc[8][8];
    #pragma unroll
    for (int i = 0; i < 8; i++)
        #pragma unroll
        for (int j = 0; j < 8; j++) acc[i][j] = 0.f;

    const int tx = threadIdx.x & 15;
    const int ty = threadIdx.x >> 4;
    const int nblk = blockIdx.x * 128;

    #pragma unroll 1
    for (int phase = 0; phase < 2; phase++) {
        const float* W = phase ? p.W2 : p.W1;
        const int K = phase ? p.K2 : p.K1;
        const float* const* sAp = phase ? sA2 : sA1;
        if (K == 0) continue;
        #pragma unroll 1
        for (int k0 = 0; k0 < K; k0 += 8) {
            // load A tile (gathered rows; scalar loads — pointers may be 8B aligned)
            {
                int row = threadIdx.x >> 1;
                int kb = (threadIdx.x & 1) * 4;
                const float* ap = sAp[row];
                #pragma unroll
                for (int j = 0; j < 4; j++) {
                    int k = k0 + kb + j;
                    As[kb + j][row] = (ap != nullptr && k < K) ? __ldg(ap + k) : 0.f;
                }
            }
            // load B tile (weights; always 16B aligned)
            {
                int kk = threadIdx.x >> 5;
                int nb = (threadIdx.x & 31) * 4;
                int k = k0 + kk;
                float4 v = make_float4(0.f, 0.f, 0.f, 0.f);
                if (k < K)
                    v = *reinterpret_cast<const float4*>(W + (size_t)k * p.ldw + nblk + nb);
                *reinterpret_cast<float4*>(&Bs[kk][nb]) = v;
            }
            __syncthreads();
            #pragma unroll
            for (int kk = 0; kk < 8; kk++) {
                float a[8], b[8];
                #pragma unroll
                for (int i = 0; i < 8; i++) a[i] = As[kk][ty * 8 + i];
                #pragma unroll
                for (int j = 0; j < 8; j++) b[j] = Bs[kk][tx * 8 + j];
                #pragma unroll
                for (int i = 0; i < 8; i++)
                    #pragma unroll
                    for (int j = 0; j < 8; j++) acc[i][j] += a[i] * b[j];
            }
            __syncthreads();
        }
    }

    // epilogue: + bias + per-row additive + optional tanh, scatter store
    #pragma unroll
    for (int i = 0; i < 8; i++) {
        int lr = ty * 8 + i;
        float* oA = sOA[lr];
        if (oA == nullptr) continue;
        float* oB = sOB[lr];
        const float* ad = sAdd[lr];
        #pragma unroll
        for (int j = 0; j < 8; j++) {
            int col = nblk + tx * 8 + j;
            float v = acc[i][j];
            if (p.bias) v += p.bias[col];
            if (ad)     v += ad[col];
            if (DOTANH) v = tanhf(v);
            if (col < 1024) oA[col] = v;
            else            oB[col - 1024] = v;
        }
    }
}

// Final classifier: out[b,n,c] = tanh(down.clfW[:1024] + up.clfW[1024:] + b)
// One warp per (b,n) row; memory-bound on reading down/up.
__global__ __launch_bounds__(256) void clf_kernel(const float* __restrict__ clfW,
                                                  const float* __restrict__ clfb,
                                                  float* __restrict__ out) {
    int row = blockIdx.x * 8 + (threadIdx.x >> 5);
    if (row >= BB * NSEQ) return;
    int lane = threadIdx.x & 31;
    const float* dn = g_down + (size_t)row * HH;
    const float* up = g_up   + (size_t)row * HH;
    float s0 = 0.f, s1 = 0.f, s2 = 0.f;
    for (int k = lane; k < HH; k += 32) {
        float d = dn[k];
        const float* w = clfW + (size_t)k * 3;
        s0 += d * w[0]; s1 += d * w[1]; s2 += d * w[2];
        float u = up[k];
        const float* w2 = clfW + (size_t)(k + HH) * 3;
        s0 += u * w2[0]; s1 += u * w2[1]; s2 += u * w2[2];
    }
    #pragma unroll
    for (int o = 16; o > 0; o >>= 1) {
        s0 += __shfl_xor_sync(0xFFFFFFFFu, s0, o);
        s1 += __shfl_xor_sync(0xFFFFFFFFu, s1, o);
        s2 += __shfl_xor_sync(0xFFFFFFFFu, s2, o);
    }
    if (lane == 0) {
        out[(size_t)row * 3 + 0] = tanhf(s0 + clfb[0]);
        out[(size_t)row * 3 + 1] = tanhf(s1 + clfb[1]);
        out[(size_t)row * 3 + 2] = tanhf(s2 + clfb[2]);
    }
}

extern "C" void kernel_launch(void* const* d_in, const int* in_sizes, int n_in,
                              void* d_out, int out_size) {
    (void)in_sizes; (void)n_in; (void)out_size;
    const int*   x     = (const int*)  d_in[0];
    const int*   wi    = (const int*)  d_in[1];
    const int*   cue   = (const int*)  d_in[2];
    // d_in[3] = adj  (unused by reference)
    const int*   pos   = (const int*)  d_in[4];
    // d_in[5] = pre_embs (unused)
    const float* wemb  = (const float*)d_in[6];
    const float* syn   = (const float*)d_in[7];
    const float* leafW = (const float*)d_in[8];
    const float* leafb = (const float*)d_in[9];
    const float* compW = (const float*)d_in[10];
    const float* compb = (const float*)d_in[11];
    const float* grevW = (const float*)d_in[12];
    const float* grevb = (const float*)d_in[13];
    const float* decW  = (const float*)d_in[14];
    const float* decb  = (const float*)d_in[15];
    const float* clfW  = (const float*)d_in[16];
    const float* clfb  = (const float*)d_in[17];
    float* out = (float*)d_out;

    P p{};
    p.x = x; p.wi = wi; p.cue = cue; p.pos = pos;
    p.syn = syn; p.wemb = wemb; p.leafW = leafW;
    p.node_base = 0; p.node_cnt = 1;

    // 1) leaf: x_emb -> up[leaves]
    {
        P q = p;
        q.W1 = leafW;                      // rows 0..1023 (word)
        q.W2 = leafW + (size_t)(HH + 3) * HH; // rows 1027..1076 (pos)
        q.bias = leafb;
        q.ldw = HH; q.K1 = HH; q.K2 = SHD; q.M = BB * LL; q.Nout = HH;
        tree_gemm<M_LEAF, false><<<dim3(8, (q.M + 127) / 128), 256>>>(q);
    }
    // 2) pre_comp = syn_emb[x[node]] @ comp_W[0:50] + comp_b
    {
        P q = p;
        q.W1 = compW; q.W2 = nullptr; q.bias = compb;
        q.ldw = HH; q.K1 = SHD; q.K2 = 0; q.M = BB * INTN; q.Nout = HH;
        tree_gemm<M_PREC, false><<<dim3(8, (q.M + 127) / 128), 256>>>(q);
    }
    // 3) pre_dec = cons_l@dec_W[0:50] + cons_r@dec_W[50:100] + dec_b
    {
        P q = p;
        q.W1 = decW; q.W2 = decW + (size_t)SHD * 2048; q.bias = decb;
        q.ldw = 2048; q.K1 = SHD; q.K2 = SHD; q.M = BB * INTN; q.Nout = 2048;
        tree_gemm<M_PRED, false><<<dim3(16, (q.M + 127) / 128), 256>>>(q);
    }
    // 4) up pass, lvl 8..0
    for (int lvl = 8; lvl >= 0; lvl--) {
        int cnt = 1 << lvl;
        P q = p;
        q.W1 = compW + (size_t)SHD * HH;          // rows 50..1073  (up_l)
        q.W2 = compW + (size_t)(SHD + HH) * HH;   // rows 1074..2097 (up_r)
        q.bias = nullptr;
        q.ldw = HH; q.K1 = HH; q.K2 = HH; q.Nout = HH;
        q.node_base = cnt - 1; q.node_cnt = cnt; q.M = BB * cnt;
        tree_gemm<M_UP, true><<<dim3(8, (q.M + 127) / 128), 256>>>(q);
    }
    // 5) grev: root -> down[:,0]
    {
        P q = p;
        q.W1 = grevW; q.W2 = grevW + (size_t)HH * HH; q.bias = grevb;
        q.ldw = HH; q.K1 = HH; q.K2 = SHD; q.M = BB; q.Nout = HH;
        tree_gemm<M_GREV, true><<<dim3(8, 1), 256>>>(q);
    }
    // 6) down pass, lvl 0..8
    for (int lvl = 0; lvl < 9; lvl++) {
        int cnt = 1 << lvl;
        P q = p;
        q.W1 = decW + (size_t)(2 * SHD) * 2048;        // rows 100..1123  (down_n)
        q.W2 = decW + (size_t)(2 * SHD + HH) * 2048;   // rows 1124..2147 (up_n)
        q.bias = nullptr;
        q.ldw = 2048; q.K1 = HH; q.K2 = HH; q.Nout = 2048;
        q.node_base = cnt - 1; q.node_cnt = cnt; q.M = BB * cnt;
        tree_gemm<M_DOWN, true><<<dim3(16, (q.M + 127) / 128), 256>>>(q);
    }
    // 7) classifier
    {
        int rows = BB * NSEQ;
        clf_kernel<<<(rows + 7) / 8, 256>>>(clfW, clfb, out);
    }
}

// round 3
// speedup vs baseline: 3.1825x; 3.1825x over previous
#include <cuda_runtime.h>
#include <cstdint>
#include <math.h>

#define BB   32
#define NSEQ 1023
#define LL   512
#define HH   1024
#define SHD  50

#define MT   128
#define NTILE 128
#define BK   32

#define AS_PAD 36
#define BS_PAD 132
#define AS_FLOATS (MT * AS_PAD)          /* per stage */
#define BS_FLOATS (BK * BS_PAD)
#define DSMEM ((2 * AS_FLOATS + 2 * BS_FLOATS) * 4)

// ---------------- scratch (device globals; no runtime alloc) ----------------
__device__ float g_up  [(size_t)BB * NSEQ * HH];
__device__ float g_down[(size_t)BB * NSEQ * HH];

// ---------------- helpers ----------------
__device__ __forceinline__ uint32_t smem_u32(const void* p) {
    uint32_t a;
    asm("{ .reg .u64 t; cvta.to.shared.u64 t, %1; cvt.u32.u64 %0, t; }" : "=r"(a) : "l"(p));
    return a;
}
__device__ __forceinline__ uint32_t rna_tf32(float x) {
    uint32_t u;
    asm("cvt.rna.tf32.f32 %0, %1;" : "=r"(u) : "f"(x));
    return u;
}
#define CP_ASYNC(dst, src, srcbytes) \
    asm volatile("cp.async.cg.shared.global [%0], [%1], 16, %2;" \
                 :: "r"(dst), "l"(src), "r"(srcbytes))
#define CP_COMMIT() asm volatile("cp.async.commit_group;" ::: "memory")
#define CP_WAIT1()  asm volatile("cp.async.wait_group 1;" ::: "memory")
#define CP_WAIT0()  asm volatile("cp.async.wait_group 0;" ::: "memory")

__device__ __forceinline__ void mma_tf32(float* c, const uint32_t* a, const uint32_t* b) {
    asm volatile(
        "mma.sync.aligned.m16n8k8.row.col.f32.tf32.tf32.f32 "
        "{%0,%1,%2,%3}, {%4,%5,%6,%7}, {%8,%9}, {%0,%1,%2,%3};"
        : "+f"(c[0]), "+f"(c[1]), "+f"(c[2]), "+f"(c[3])
        : "r"(a[0]), "r"(a[1]), "r"(a[2]), "r"(a[3]), "r"(b[0]), "r"(b[1]));
}

enum { M_LEAF = 0, M_UP, M_GREV, M_DOWN };

struct GP {
    const float* W; const float* bias;
    int ldw, M, nph, node_base, node_cnt;
    int ph_start[5]; int ph_K[4]; int ph_w0[4];
    const int *x, *cue, *pos;
    const float *syn, *wemb, *leafW;
};

// ---------------- main GEMM: gathered A, phased K, fused epilogue ----------------
template<int MODE, bool DOTANH>
__global__ __launch_bounds__(256) void tc_gemm(GP p) {
    __shared__ const float* sA[4][MT];
    __shared__ float* sO[MT];
    __shared__ const float* sAdd[MT];
    extern __shared__ float dyn[];
    float* As = dyn;                       // 2 stages of [MT][AS_PAD]
    float* Bs = dyn + 2 * AS_FLOATS;       // 2 stages of [BK][BS_PAD]

    const int tid = threadIdx.x;
    const int wid = tid >> 5;
    const int lane = tid & 31;
    const int rbase = blockIdx.y * MT;
    const int nblk = blockIdx.x * NTILE;

    // prologue: gathered A-row pointers, output pointers, additive rows
    for (int t = tid; t < MT; t += 256) {
        int r = rbase + t;
        const float *a0 = nullptr, *a1 = nullptr, *a2 = nullptr, *a3 = nullptr, *ad = nullptr;
        float* o = nullptr;
        if (r < p.M) {
            if (MODE == M_LEAF) {
                int b = r >> 9, l = r & (LL - 1);
                int w = (LL - 1) + l;
                int s = p.x[b * NSEQ + w];
                int c = p.cue[b * NSEQ + w];
                a0 = p.wemb + (size_t)s * HH;
                a1 = p.syn + (size_t)p.pos[b * LL + l] * SHD;
                ad = p.leafW + (size_t)(HH + c) * HH;
                o  = g_up + ((size_t)b * NSEQ + w) * HH;
            } else if (MODE == M_UP) {
                int b = r / p.node_cnt, n = p.node_base + r % p.node_cnt;
                a0 = p.syn + (size_t)p.x[b * NSEQ + n] * SHD;
                a1 = g_up + ((size_t)b * NSEQ + 2 * n + 1) * HH;   // [up_l;up_r] contiguous
                o  = g_up + ((size_t)b * NSEQ + n) * HH;
            } else if (MODE == M_GREV) {
                int b = r;
                a0 = g_up + (size_t)b * NSEQ * HH;
                a1 = p.syn + (size_t)p.x[b * NSEQ] * SHD;
                o  = g_down + (size_t)b * NSEQ * HH;
            } else { // M_DOWN
                int b = r / p.node_cnt, n = p.node_base + r % p.node_cnt;
                int cl = 2 * n + 1, cr = 2 * n + 2;
                int il = (cl >= LL - 1) ? p.pos[b * LL + cl - (LL - 1)] : p.x[b * NSEQ + cl];
                int ir = (cr >= LL - 1) ? p.pos[b * LL + cr - (LL - 1)] : p.x[b * NSEQ + cr];
                a0 = p.syn + (size_t)il * SHD;
                a1 = p.syn + (size_t)ir * SHD;
                a2 = g_down + ((size_t)b * NSEQ + n) * HH;
                a3 = g_up + ((size_t)b * NSEQ + n) * HH;
                o  = g_down + ((size_t)b * NSEQ + cl) * HH;        // 2048 cols contiguous
            }
        }
        sA[0][t] = a0; sA[1][t] = a1; sA[2][t] = a2; sA[3][t] = a3;
        sO[t] = o; sAdd[t] = ad;
    }
    __syncthreads();

    const int nc = p.ph_start[p.nph];

    // per-thread A staging assignment: row = tid>>1, 16 consecutive k
    const int am = tid >> 1;
    const int akb = (tid & 1) * 16;

    // B cp.async assignment: 4 transfers of 16B per thread
    // linear = i*256 + tid; row = linear>>5; col = (linear&31)*4 floats
    auto prefetchB = [&](int c, int stage) {
        int phidx = 0;
        #pragma unroll
        for (int q = 1; q < 4; q++) if (q < p.nph && c >= p.ph_start[q]) phidx = q;
        const int kloc0 = (c - p.ph_start[phidx]) * BK;
        const int Kseg = p.ph_K[phidx];
        const int w0 = p.ph_w0[phidx];
        float* bs = Bs + stage * BS_FLOATS;
        #pragma unroll
        for (int i = 0; i < 4; i++) {
            int linear = i * 256 + tid;
            int row = linear >> 5;
            int col = (linear & 31) * 4;
            bool valid = (kloc0 + row) < Kseg;
            const float* src = p.W + (size_t)(w0 + (valid ? kloc0 + row : 0)) * p.ldw + nblk + col;
            uint32_t dst = smem_u32(bs + row * BS_PAD + col);
            CP_ASYNC(dst, src, valid ? 16 : 0);
        }
    };

    auto loadA = [&](int c, uint32_t* ar) {
        int phidx = 0;
        #pragma unroll
        for (int q = 1; q < 4; q++) if (q < p.nph && c >= p.ph_start[q]) phidx = q;
        const int kloc0 = (c - p.ph_start[phidx]) * BK;
        const int Kseg = p.ph_K[phidx];
        const float* ap = sA[phidx][am];
        const float* base = ap ? ap + kloc0 + akb : nullptr;
        const bool alig = base && ((((uintptr_t)base) & 15) == 0);
        #pragma unroll
        for (int g = 0; g < 4; g++) {
            int k = kloc0 + akb + g * 4;   // phase-local k of first element
            float4 v = make_float4(0.f, 0.f, 0.f, 0.f);
            if (base) {
                if (alig && (k + 3) < Kseg) {
                    v = *reinterpret_cast<const float4*>(base + g * 4);
                } else {
                    if (k     < Kseg) v.x = __ldg(base + g * 4);
                    if (k + 1 < Kseg) v.y = __ldg(base + g * 4 + 1);
                    if (k + 2 < Kseg) v.z = __ldg(base + g * 4 + 2);
                    if (k + 3 < Kseg) v.w = __ldg(base + g * 4 + 3);
                }
            }
            ar[g * 4 + 0] = rna_tf32(v.x);
            ar[g * 4 + 1] = rna_tf32(v.y);
            ar[g * 4 + 2] = rna_tf32(v.z);
            ar[g * 4 + 3] = rna_tf32(v.w);
        }
    };

    // accumulators: warp grid 2(M) x 4(N); warp tile 64x32
    const int warp_m = wid & 1;
    const int warp_n = wid >> 1;
    float cacc[4][4][4];
    #pragma unroll
    for (int i = 0; i < 4; i++)
        #pragma unroll
        for (int j = 0; j < 4; j++)
            #pragma unroll
            for (int e = 0; e < 4; e++) cacc[i][j][e] = 0.f;

    uint32_t ar[16], ar2[16];

    prefetchB(0, 0);
    CP_COMMIT();
    loadA(0, ar);

    for (int c = 0; c < nc; c++) {
        const int stage = c & 1;
        // STS A(c)
        {
            float* as = As + stage * AS_FLOATS + am * AS_PAD + akb;
            #pragma unroll
            for (int g = 0; g < 4; g++)
                *reinterpret_cast<uint4*>(as + g * 4) =
                    *reinterpret_cast<const uint4*>(&ar[g * 4]);
        }
        if (c + 1 < nc) {
            prefetchB(c + 1, stage ^ 1);
            CP_COMMIT();
            loadA(c + 1, ar2);
            CP_WAIT1();
        } else {
            CP_WAIT0();
        }
        __syncthreads();

        // compute chunk c
        {
            const float* as = As + stage * AS_FLOATS;
            const float* bs = Bs + stage * BS_FLOATS;
            const int gid = lane >> 2;     // 0..7
            const int tig = lane & 3;      // 0..3
            #pragma unroll
            for (int kk = 0; kk < 4; kk++) {
                uint32_t af[4][4];
                #pragma unroll
                for (int mf = 0; mf < 4; mf++) {
                    int r1 = warp_m * 64 + mf * 16 + gid;
                    int k1 = kk * 8 + tig;
                    const float* a1p = as + r1 * AS_PAD + k1;
                    const float* a2p = as + (r1 + 8) * AS_PAD + k1;
                    af[mf][0] = __float_as_uint(a1p[0]);
                    af[mf][1] = __float_as_uint(a2p[0]);
                    af[mf][2] = __float_as_uint(a1p[4]);
                    af[mf][3] = __float_as_uint(a2p[4]);
                }
                uint32_t bf[4][2];
                #pragma unroll
                for (int nf = 0; nf < 4; nf++) {
                    int n = warp_n * 32 + nf * 8 + gid;
                    int k1 = kk * 8 + tig;
                    bf[nf][0] = rna_tf32(bs[k1 * BS_PAD + n]);
                    bf[nf][1] = rna_tf32(bs[(k1 + 4) * BS_PAD + n]);
                }
                #pragma unroll
                for (int mf = 0; mf < 4; mf++)
                    #pragma unroll
                    for (int nf = 0; nf < 4; nf++)
                        mma_tf32(cacc[mf][nf], af[mf], bf[nf]);
            }
        }
        __syncthreads();
        #pragma unroll
        for (int j = 0; j < 16; j++) ar[j] = ar2[j];
    }

    // epilogue: bias + additive row + tanh, float2 stores
    {
        const int gid = lane >> 2;
        const int tig = lane & 3;
        #pragma unroll
        for (int mf = 0; mf < 4; mf++) {
            const int tr1 = warp_m * 64 + mf * 16 + gid;
            const int tr2 = tr1 + 8;
            float* o1 = sO[tr1];
            float* o2 = sO[tr2];
            const float* ad1 = sAdd[tr1];
            const float* ad2 = sAdd[tr2];
            #pragma unroll
            for (int nf = 0; nf < 4; nf++) {
                const int col0 = nblk + warp_n * 32 + nf * 8 + tig * 2;
                float b0 = p.bias[col0], b1 = p.bias[col0 + 1];
                if (o1) {
                    float v0 = cacc[mf][nf][0] + b0;
                    float v1 = cacc[mf][nf][1] + b1;
                    if (ad1) { v0 += ad1[col0]; v1 += ad1[col0 + 1]; }
                    if (DOTANH) { v0 = tanhf(v0); v1 = tanhf(v1); }
                    *reinterpret_cast<float2*>(o1 + col0) = make_float2(v0, v1);
                }
                if (o2) {
                    float v0 = cacc[mf][nf][2] + b0;
                    float v1 = cacc[mf][nf][3] + b1;
                    if (ad2) { v0 += ad2[col0]; v1 += ad2[col0 + 1]; }
                    if (DOTANH) { v0 = tanhf(v0); v1 = tanhf(v1); }
                    *reinterpret_cast<float2*>(o2 + col0) = make_float2(v0, v1);
                }
            }
        }
    }
}

// ---------------- classifier (memory-bound) ----------------
__global__ __launch_bounds__(256) void clf_kernel(const float* __restrict__ clfW,
                                                  const float* __restrict__ clfb,
                                                  float* __restrict__ out) {
    int row = blockIdx.x * 8 + (threadIdx.x >> 5);
    if (row >= BB * NSEQ) return;
    int lane = threadIdx.x & 31;
    const float* dn = g_down + (size_t)row * HH;
    const float* up = g_up + (size_t)row * HH;
    float s0 = 0.f, s1 = 0.f, s2 = 0.f;
    for (int k = lane * 4; k < HH; k += 128) {
        float4 d = *reinterpret_cast<const float4*>(dn + k);
        float4 u = *reinterpret_cast<const float4*>(up + k);
        const float* dd = &d.x;
        const float* uu = &u.x;
        #pragma unroll
        for (int e = 0; e < 4; e++) {
            const float* w  = clfW + (size_t)(k + e) * 3;
            const float* w2 = clfW + (size_t)(k + e + HH) * 3;
            s0 += dd[e] * w[0] + uu[e] * w2[0];
            s1 += dd[e] * w[1] + uu[e] * w2[1];
            s2 += dd[e] * w[2] + uu[e] * w2[2];
        }
    }
    #pragma unroll
    for (int o = 16; o > 0; o >>= 1) {
        s0 += __shfl_xor_sync(0xFFFFFFFFu, s0, o);
        s1 += __shfl_xor_sync(0xFFFFFFFFu, s1, o);
        s2 += __shfl_xor_sync(0xFFFFFFFFu, s2, o);
    }
    if (lane == 0) {
        out[(size_t)row * 3 + 0] = tanhf(s0 + clfb[0]);
        out[(size_t)row * 3 + 1] = tanhf(s1 + clfb[1]);
        out[(size_t)row * 3 + 2] = tanhf(s2 + clfb[2]);
    }
}

// ---------------- host ----------------
extern "C" void kernel_launch(void* const* d_in, const int* in_sizes, int n_in,
                              void* d_out, int out_size) {
    (void)in_sizes; (void)n_in; (void)out_size;
    const int*   x     = (const int*)  d_in[0];
    const int*   cue   = (const int*)  d_in[2];
    const int*   pos   = (const int*)  d_in[4];
    const float* wemb  = (const float*)d_in[6];
    const float* syn   = (const float*)d_in[7];
    const float* leafW = (const float*)d_in[8];
    const float* leafb = (const float*)d_in[9];
    const float* compW = (const float*)d_in[10];
    const float* compb = (const float*)d_in[11];
    const float* grevW = (const float*)d_in[12];
    const float* grevb = (const float*)d_in[13];
    const float* decW  = (const float*)d_in[14];
    const float* decb  = (const float*)d_in[15];
    const float* clfW  = (const float*)d_in[16];
    const float* clfb  = (const float*)d_in[17];
    float* out = (float*)d_out;

    static bool attr_done = false;
    if (!attr_done) {
        cudaFuncSetAttribute(tc_gemm<M_LEAF, false>, cudaFuncAttributeMaxDynamicSharedMemorySize, DSMEM);
        cudaFuncSetAttribute(tc_gemm<M_UP,   true>,  cudaFuncAttributeMaxDynamicSharedMemorySize, DSMEM);
        cudaFuncSetAttribute(tc_gemm<M_GREV, true>,  cudaFuncAttributeMaxDynamicSharedMemorySize, DSMEM);
        cudaFuncSetAttribute(tc_gemm<M_DOWN, true>,  cudaFuncAttributeMaxDynamicSharedMemorySize, DSMEM);
        attr_done = true;
    }

    GP base{};
    base.x = x; base.cue = cue; base.pos = pos;
    base.syn = syn; base.wemb = wemb; base.leafW = leafW;
    base.node_base = 0; base.node_cnt = 1;

    // leaf: up[leaves] = x_emb @ leaf_W + leaf_b   (word K=1024, pos K=50, cue = add row)
    {
        GP q = base;
        q.W = leafW; q.bias = leafb; q.ldw = 1024;
        q.M = BB * LL; q.nph = 2;
        q.ph_start[0] = 0; q.ph_start[1] = 32; q.ph_start[2] = 34;
        q.ph_start[3] = 1 << 20; q.ph_start[4] = 1 << 20;
        q.ph_K[0] = 1024; q.ph_K[1] = 50;
        q.ph_w0[0] = 0;   q.ph_w0[1] = 1027;
        tc_gemm<M_LEAF, false><<<dim3(8, (q.M + MT - 1) / MT), 256, DSMEM>>>(q);
    }
    // up pass
    for (int lvl = 8; lvl >= 0; lvl--) {
        int cnt = 1 << lvl;
        GP q = base;
        q.W = compW; q.bias = compb; q.ldw = 1024;
        q.M = BB * cnt; q.nph = 2;
        q.node_base = cnt - 1; q.node_cnt = cnt;
        q.ph_start[0] = 0; q.ph_start[1] = 2; q.ph_start[2] = 66;
        q.ph_start[3] = 1 << 20; q.ph_start[4] = 1 << 20;
        q.ph_K[0] = 50;  q.ph_K[1] = 2048;
        q.ph_w0[0] = 0;  q.ph_w0[1] = 50;
        tc_gemm<M_UP, true><<<dim3(8, (q.M + MT - 1) / MT), 256, DSMEM>>>(q);
    }
    // grev (root -> down[:,0])
    {
        GP q = base;
        q.W = grevW; q.bias = grevb; q.ldw = 1024;
        q.M = BB; q.nph = 2;
        q.ph_start[0] = 0; q.ph_start[1] = 32; q.ph_start[2] = 34;
        q.ph_start[3] = 1 << 20; q.ph_start[4] = 1 << 20;
        q.ph_K[0] = 1024; q.ph_K[1] = 50;
        q.ph_w0[0] = 0;   q.ph_w0[1] = 1024;
        tc_gemm<M_GREV, true><<<dim3(8, 1), 256, DSMEM>>>(q);
    }
    // down pass
    for (int lvl = 0; lvl < 9; lvl++) {
        int cnt = 1 << lvl;
        GP q = base;
        q.W = decW; q.bias = decb; q.ldw = 2048;
        q.M = BB * cnt; q.nph = 4;
        q.node_base = cnt - 1; q.node_cnt = cnt;
        q.ph_start[0] = 0; q.ph_start[1] = 2; q.ph_start[2] = 4;
        q.ph_start[3] = 36; q.ph_start[4] = 68;
        q.ph_K[0] = 50;  q.ph_K[1] = 50;  q.ph_K[2] = 1024; q.ph_K[3] = 1024;
        q.ph_w0[0] = 0;  q.ph_w0[1] = 50; q.ph_w0[2] = 100; q.ph_w0[3] = 1124;
        tc_gemm<M_DOWN, true><<<dim3(16, (q.M + MT - 1) / MT), 256, DSMEM>>>(q);
    }
    // classifier
    clf_kernel<<<(BB * NSEQ + 7) / 8, 256>>>(clfW, clfb, out);
}

// round 4
// speedup vs baseline: 3.4916x; 1.0971x over previous
#include <cuda_runtime.h>
#include <cstdint>
#include <math.h>

#define BB   32
#define NSEQ 1023
#define LL   512
#define HH   1024
#define SHD  50
#define SYNR 128

#define MT    128
#define NTILE 256
#define BK    32
#define STAGES 4

#define AS_PAD 36
#define BS_PAD 264
#define AS_FLOATS (MT * AS_PAD)
#define BS_FLOATS (BK * BS_PAD)
#define STAGE_FLOATS (AS_FLOATS + BS_FLOATS)
#define DSMEM (STAGES * STAGE_FLOATS * 4)

// K-padded scratch layouts
#define KP_COMP 2112   /* 64(syn) + 2048 */
#define KP_DEC  2176   /* 64 + 64 + 2048 */
#define KP_LG   1088   /* 1024 + 64 */

// ---------------- scratch (device globals; no runtime alloc) ----------------
__device__ float g_up   [(size_t)BB * NSEQ * HH];
__device__ float g_down [(size_t)BB * NSEQ * HH];
__device__ float g_wcomp[(size_t)KP_COMP * 1024];
__device__ float g_wdec [(size_t)KP_DEC  * 2048];
__device__ float g_wleaf[(size_t)KP_LG   * 1024];
__device__ float g_wgrev[(size_t)KP_LG   * 1024];
__device__ float g_syn  [(size_t)SYNR * 64];
__device__ float g_leafA[(size_t)BB * LL * KP_LG];

// ---------------- helpers ----------------
__device__ __forceinline__ uint32_t smem_u32(const void* p) {
    uint32_t a;
    asm("{ .reg .u64 t; cvta.to.shared.u64 t, %1; cvt.u32.u64 %0, t; }" : "=r"(a) : "l"(p));
    return a;
}
__device__ __forceinline__ float rna_tf32f(float x) {
    uint32_t u;
    asm("cvt.rna.tf32.f32 %0, %1;" : "=r"(u) : "f"(x));
    return __uint_as_float(u);
}
#define CP_ASYNC16(dst, src) \
    asm volatile("cp.async.cg.shared.global [%0], [%1], 16;" :: "r"(dst), "l"(src))
#define CP_COMMIT() asm volatile("cp.async.commit_group;" ::: "memory")
#define CP_WAIT(n)  asm volatile("cp.async.wait_group %0;" :: "n"(n) : "memory")

__device__ __forceinline__ void mma_tf32(float* c, const uint32_t* a, const uint32_t* b) {
    asm volatile(
        "mma.sync.aligned.m16n8k8.row.col.f32.tf32.tf32.f32 "
        "{%0,%1,%2,%3}, {%4,%5,%6,%7}, {%8,%9}, {%0,%1,%2,%3};"
        : "+f"(c[0]), "+f"(c[1]), "+f"(c[2]), "+f"(c[3])
        : "r"(a[0]), "r"(a[1]), "r"(a[2]), "r"(a[3]), "r"(b[0]), "r"(b[1]));
}

enum { M_LEAF = 0, M_UP, M_GREV, M_DOWN };

struct GP {
    const float* W;       // padded, pre-rounded, [Ktot][ldw]
    const float* bias;
    int ldw, M, Ktot, nph, node_base, node_cnt;
    int ph_start[5];      // chunk index where each A-phase begins
    const int *x, *cue;
    const float* leafW;   // raw, for cue additive rows
};

// ---------------- prep kernels ----------------
__global__ void zero_scratch() {
    const size_t n0 = (size_t)KP_COMP * 1024, n1 = (size_t)KP_DEC * 2048,
                 n2 = (size_t)KP_LG * 1024, n3 = (size_t)SYNR * 64;
    const size_t total = n0 + n1 + 2 * n2 + n3;
    for (size_t i = (size_t)blockIdx.x * blockDim.x + threadIdx.x; i < total;
         i += (size_t)gridDim.x * blockDim.x) {
        if (i < n0) g_wcomp[i] = 0.f;
        else if (i < n0 + n1) g_wdec[i - n0] = 0.f;
        else if (i < n0 + n1 + n2) g_wleaf[i - n0 - n1] = 0.f;
        else if (i < n0 + n1 + 2 * n2) g_wgrev[i - n0 - n1 - n2] = 0.f;
        else g_syn[i - n0 - n1 - 2 * n2] = 0.f;
    }
}

// dst[(row0+r)*ldd + c] = rna(src[r*lds + c])
__global__ void copyRound(float* __restrict__ dst, int ldd, int row0,
                          const float* __restrict__ src, int lds,
                          int rows, int cols) {
    size_t total = (size_t)rows * cols;
    for (size_t i = (size_t)blockIdx.x * blockDim.x + threadIdx.x; i < total;
         i += (size_t)gridDim.x * blockDim.x) {
        int r = (int)(i / cols), c = (int)(i % cols);
        dst[(size_t)(row0 + r) * ldd + c] = rna_tf32f(src[(size_t)r * lds + c]);
    }
}

// build gathered+rounded leaf A rows: [wemb[s] (1024, rna) | g_syn[pos] (64)]
__global__ __launch_bounds__(256) void build_leafA(const int* __restrict__ x,
                                                   const int* __restrict__ pos,
                                                   const float* __restrict__ wemb) {
    int row = blockIdx.x * 8 + (threadIdx.x >> 5);
    if (row >= BB * LL) return;
    int lane = threadIdx.x & 31;
    int b = row >> 9, l = row & (LL - 1);
    int w = (LL - 1) + l;
    int s = x[b * NSEQ + w];
    int pr = pos[b * LL + l];
    const float4* src = reinterpret_cast<const float4*>(wemb + (size_t)s * HH);
    float* dst = g_leafA + (size_t)row * KP_LG;
    #pragma unroll
    for (int i = 0; i < 8; i++) {
        float4 v = src[lane + i * 32];
        v.x = rna_tf32f(v.x); v.y = rna_tf32f(v.y);
        v.z = rna_tf32f(v.z); v.w = rna_tf32f(v.w);
        reinterpret_cast<float4*>(dst)[lane + i * 32] = v;
    }
    if (lane < 16)
        reinterpret_cast<float4*>(dst + 1024)[lane] =
            reinterpret_cast<const float4*>(g_syn + (size_t)pr * 64)[lane];
}

// ---------------- main GEMM v2: pure cp.async, phased gathered A ----------------
template<int MODE, bool DOTANH>
__global__ __launch_bounds__(256) void tc_gemm2(GP p) {
    __shared__ const float* sAp[4][MT];
    __shared__ float* sO[MT];
    __shared__ const float* sAdd[MT];
    extern __shared__ float dyn[];

    const int tid = threadIdx.x;
    const int wid = tid >> 5;
    const int lane = tid & 31;
    const int rbase = blockIdx.y * MT;
    const int nblk = blockIdx.x * NTILE;

    // prologue: row pointer tables
    for (int t = tid; t < MT; t += 256) {
        int r = rbase + t;
        const float *a0 = p.W, *a1 = p.W, *a2 = p.W, *a3 = p.W, *ad = nullptr;
        float* o = nullptr;
        if (r < p.M) {
            if (MODE == M_LEAF) {
                int b = r >> 9, l = r & (LL - 1);
                int w = (LL - 1) + l;
                int c = p.cue[b * NSEQ + w];
                a0 = g_leafA + (size_t)r * KP_LG;
                ad = p.leafW + (size_t)(HH + c) * HH;
                o  = g_up + ((size_t)b * NSEQ + w) * HH;
            } else if (MODE == M_UP) {
                int b = r / p.node_cnt, n = p.node_base + r % p.node_cnt;
                a0 = g_syn + (size_t)p.x[b * NSEQ + n] * 64;
                a1 = g_up + ((size_t)b * NSEQ + 2 * n + 1) * HH;   // [up_l;up_r]
                o  = g_up + ((size_t)b * NSEQ + n) * HH;
            } else if (MODE == M_GREV) {
                int b = r;
                a0 = g_up + (size_t)b * NSEQ * HH;
                a1 = g_syn + (size_t)p.x[b * NSEQ] * 64;
                o  = g_down + (size_t)b * NSEQ * HH;
            } else { // M_DOWN
                int b = r / p.node_cnt, n = p.node_base + r % p.node_cnt;
                int cl = 2 * n + 1, cr = 2 * n + 2;
                int il = (cl >= LL - 1) ? 0 : p.x[b * NSEQ + cl];
                int ir = (cr >= LL - 1) ? 0 : p.x[b * NSEQ + cr];
                // leaf children use pos rows; internal use x rows
                if (cl >= LL - 1) {
                    // pos index for leaf cl: pos[b][cl-(L-1)]; stored in cue? no — use x? need pos
                    // handled below via ppos
                }
                a2 = g_down + ((size_t)b * NSEQ + n) * HH;
                a3 = g_up + ((size_t)b * NSEQ + n) * HH;
                // syn row indices (x or pos):
                {
                    const int* xx = p.x;
                    const int* pp = p.cue; // for M_DOWN, cue slot carries pos ptr
                    int si_l = (cl >= LL - 1) ? pp[b * LL + cl - (LL - 1)] : xx[b * NSEQ + cl];
                    int si_r = (cr >= LL - 1) ? pp[b * LL + cr - (LL - 1)] : xx[b * NSEQ + cr];
                    a0 = g_syn + (size_t)si_l * 64;
                    a1 = g_syn + (size_t)si_r * 64;
                }
                o  = g_down + ((size_t)b * NSEQ + cl) * HH;        // 2048 contiguous
                (void)il; (void)ir;
            }
        }
        sAp[0][t] = a0; sAp[1][t] = a1; sAp[2][t] = a2; sAp[3][t] = a3;
        sO[t] = o; sAdd[t] = ad;
    }
    __syncthreads();

    const int nc = p.Ktot / BK;

    // A staging: thread t -> row t>>1, 16-float half (t&1)
    const int am = tid >> 1;
    const int ahalf = (tid & 1) * 16;

    auto prefetch = [&](int c, int stage) {
        float* as = dyn + stage * STAGE_FLOATS;
        float* bs = as + AS_FLOATS;
        // A: phase select
        int phidx = 0;
        #pragma unroll
        for (int q = 1; q < 4; q++) if (q < p.nph && c >= p.ph_start[q]) phidx = q;
        const int kloc = (c - p.ph_start[phidx]) * BK;
        const float* src = sAp[phidx][am] + kloc + ahalf;
        uint32_t dstA = smem_u32(as + am * AS_PAD + ahalf);
        #pragma unroll
        for (int g = 0; g < 4; g++)
            CP_ASYNC16(dstA + g * 16, src + g * 4);
        // B: linear padded K
        const float* wsrc = p.W + (size_t)(c * BK) * p.ldw + nblk;
        #pragma unroll
        for (int i = 0; i < 8; i++) {
            int linear = i * 256 + tid;
            int row = linear >> 6;
            int col = (linear & 63) * 4;
            CP_ASYNC16(smem_u32(bs + row * BS_PAD + col),
                       wsrc + (size_t)row * p.ldw + col);
        }
    };

    // accumulators: 8 warps as 2(M) x 4(N); warp tile 64x64
    const int warp_m = wid & 1;
    const int warp_n = wid >> 1;
    const int gid = lane >> 2;
    const int tig = lane & 3;
    float cacc[4][8][4];
    #pragma unroll
    for (int i = 0; i < 4; i++)
        #pragma unroll
        for (int j = 0; j < 8; j++)
            #pragma unroll
            for (int e = 0; e < 4; e++) cacc[i][j][e] = 0.f;

    // pipeline prologue
    #pragma unroll
    for (int s = 0; s < STAGES - 1; s++) {
        if (s < nc) prefetch(s, s);
        CP_COMMIT();
    }

    for (int c = 0; c < nc; c++) {
        CP_WAIT(STAGES - 2);
        __syncthreads();
        const int stage = c & (STAGES - 1);
        const float* as = dyn + stage * STAGE_FLOATS;
        const float* bs = as + AS_FLOATS;
        #pragma unroll
        for (int kk = 0; kk < 4; kk++) {
            const int k1 = kk * 8 + tig;
            uint32_t af[4][4];
            #pragma unroll
            for (int mf = 0; mf < 4; mf++) {
                const float* ap = as + (warp_m * 64 + mf * 16 + gid) * AS_PAD + k1;
                af[mf][0] = __float_as_uint(ap[0]);
                af[mf][1] = __float_as_uint(ap[8 * AS_PAD]);
                af[mf][2] = __float_as_uint(ap[4]);
                af[mf][3] = __float_as_uint(ap[8 * AS_PAD + 4]);
            }
            uint32_t bf[8][2];
            #pragma unroll
            for (int nf = 0; nf < 8; nf++) {
                const float* bp = bs + k1 * BS_PAD + warp_n * 64 + nf * 8 + gid;
                bf[nf][0] = __float_as_uint(bp[0]);
                bf[nf][1] = __float_as_uint(bp[4 * BS_PAD]);
            }
            #pragma unroll
            for (int mf = 0; mf < 4; mf++)
                #pragma unroll
                for (int nf = 0; nf < 8; nf++)
                    mma_tf32(cacc[mf][nf], af[mf], bf[nf]);
        }
        int pc = c + STAGES - 1;
        if (pc < nc) prefetch(pc, pc & (STAGES - 1));
        CP_COMMIT();
    }

    // epilogue: bias + additive row + tanh, tf32-rounded activation stores
    #pragma unroll
    for (int mf = 0; mf < 4; mf++) {
        const int tr1 = warp_m * 64 + mf * 16 + gid;
        const int tr2 = tr1 + 8;
        float* o1 = sO[tr1];
        float* o2 = sO[tr2];
        const float* ad1 = sAdd[tr1];
        const float* ad2 = sAdd[tr2];
        #pragma unroll
        for (int nf = 0; nf < 8; nf++) {
            const int col0 = nblk + warp_n * 64 + nf * 8 + tig * 2;
            float b0 = p.bias[col0], b1 = p.bias[col0 + 1];
            if (o1) {
                float v0 = cacc[mf][nf][0] + b0;
                float v1 = cacc[mf][nf][1] + b1;
                if (MODE == M_LEAF && ad1) { v0 += ad1[col0]; v1 += ad1[col0 + 1]; }
                if (DOTANH) { v0 = tanhf(v0); v1 = tanhf(v1); }
                *reinterpret_cast<float2*>(o1 + col0) =
                    make_float2(rna_tf32f(v0), rna_tf32f(v1));
            }
            if (o2) {
                float v0 = cacc[mf][nf][2] + b0;
                float v1 = cacc[mf][nf][3] + b1;
                if (MODE == M_LEAF && ad2) { v0 += ad2[col0]; v1 += ad2[col0 + 1]; }
                if (DOTANH) { v0 = tanhf(v0); v1 = tanhf(v1); }
                *reinterpret_cast<float2*>(o2 + col0) =
                    make_float2(rna_tf32f(v0), rna_tf32f(v1));
            }
        }
    }
}

// ---------------- classifier ----------------
__global__ __launch_bounds__(256) void clf_kernel(const float* __restrict__ clfW,
                                                  const float* __restrict__ clfb,
                                                  float* __restrict__ out) {
    int row = blockIdx.x * 8 + (threadIdx.x >> 5);
    if (row >= BB * NSEQ) return;
    int lane = threadIdx.x & 31;
    const float* dn = g_down + (size_t)row * HH;
    const float* up = g_up + (size_t)row * HH;
    float s0 = 0.f, s1 = 0.f, s2 = 0.f;
    for (int k = lane * 4; k < HH; k += 128) {
        float4 d = *reinterpret_cast<const float4*>(dn + k);
        float4 u = *reinterpret_cast<const float4*>(up + k);
        const float* dd = &d.x;
        const float* uu = &u.x;
        #pragma unroll
        for (int e = 0; e < 4; e++) {
            const float* w  = clfW + (size_t)(k + e) * 3;
            const float* w2 = clfW + (size_t)(k + e + HH) * 3;
            s0 += dd[e] * w[0] + uu[e] * w2[0];
            s1 += dd[e] * w[1] + uu[e] * w2[1];
            s2 += dd[e] * w[2] + uu[e] * w2[2];
        }
    }
    #pragma unroll
    for (int o = 16; o > 0; o >>= 1) {
        s0 += __shfl_xor_sync(0xFFFFFFFFu, s0, o);
        s1 += __shfl_xor_sync(0xFFFFFFFFu, s1, o);
        s2 += __shfl_xor_sync(0xFFFFFFFFu, s2, o);
    }
    if (lane == 0) {
        out[(size_t)row * 3 + 0] = tanhf(s0 + clfb[0]);
        out[(size_t)row * 3 + 1] = tanhf(s1 + clfb[1]);
        out[(size_t)row * 3 + 2] = tanhf(s2 + clfb[2]);
    }
}

// ---------------- host ----------------
extern "C" void kernel_launch(void* const* d_in, const int* in_sizes, int n_in,
                              void* d_out, int out_size) {
    (void)in_sizes; (void)n_in; (void)out_size;
    const int*   x     = (const int*)  d_in[0];
    const int*   cue   = (const int*)  d_in[2];
    const int*   pos   = (const int*)  d_in[4];
    const float* wemb  = (const float*)d_in[6];
    const float* syn   = (const float*)d_in[7];
    const float* leafW = (const float*)d_in[8];
    const float* leafb = (const float*)d_in[9];
    const float* compW = (const float*)d_in[10];
    const float* compb = (const float*)d_in[11];
    const float* grevW = (const float*)d_in[12];
    const float* grevb = (const float*)d_in[13];
    const float* decW  = (const float*)d_in[14];
    const float* decb  = (const float*)d_in[15];
    const float* clfW  = (const float*)d_in[16];
    const float* clfb  = (const float*)d_in[17];
    float* out = (float*)d_out;

    float *wc, *wd, *wl, *wg, *sy;
    cudaGetSymbolAddress((void**)&wc, g_wcomp);
    cudaGetSymbolAddress((void**)&wd, g_wdec);
    cudaGetSymbolAddress((void**)&wl, g_wleaf);
    cudaGetSymbolAddress((void**)&wg, g_wgrev);
    cudaGetSymbolAddress((void**)&sy, g_syn);

    static bool attr_done = false;
    if (!attr_done) {
        cudaFuncSetAttribute(tc_gemm2<M_LEAF, false>, cudaFuncAttributeMaxDynamicSharedMemorySize, DSMEM);
        cudaFuncSetAttribute(tc_gemm2<M_UP,   true>,  cudaFuncAttributeMaxDynamicSharedMemorySize, DSMEM);
        cudaFuncSetAttribute(tc_gemm2<M_GREV, true>,  cudaFuncAttributeMaxDynamicSharedMemorySize, DSMEM);
        cudaFuncSetAttribute(tc_gemm2<M_DOWN, true>,  cudaFuncAttributeMaxDynamicSharedMemorySize, DSMEM);
        attr_done = true;
    }

    // ---- prep: zero pads, round+copy weights/syn, build leaf A rows ----
    zero_scratch<<<2048, 256>>>();
    auto cp = [&](float* dst, int ldd, int row0, const float* src, int lds, int rows, int cols) {
        size_t n = (size_t)rows * cols;
        int blocks = (int)((n + 255) / 256);
        if (blocks > 4096) blocks = 4096;
        copyRound<<<blocks, 256>>>(dst, ldd, row0, src, lds, rows, cols);
    };
    cp(sy, 64, 0, syn, SHD, SYNR, SHD);
    cp(wc, 1024, 0,  compW, 1024, 50, 1024);
    cp(wc, 1024, 64, compW + (size_t)50 * 1024, 1024, 2048, 1024);
    cp(wd, 2048, 0,   decW, 2048, 50, 2048);
    cp(wd, 2048, 64,  decW + (size_t)50 * 2048, 2048, 50, 2048);
    cp(wd, 2048, 128, decW + (size_t)100 * 2048, 2048, 2048, 2048);
    cp(wl, 1024, 0,    leafW, 1024, 1024, 1024);
    cp(wl, 1024, 1024, leafW + (size_t)1027 * 1024, 1024, 50, 1024);
    cp(wg, 1024, 0,    grevW, 1024, 1024, 1024);
    cp(wg, 1024, 1024, grevW + (size_t)1024 * 1024, 1024, 50, 1024);
    build_leafA<<<(BB * LL + 7) / 8, 256>>>(x, pos, wemb);

    GP base{};
    base.x = x; base.cue = cue; base.leafW = leafW;
    base.node_base = 0; base.node_cnt = 1;

    // leaf: single phase K=1088
    {
        GP q = base;
        q.W = wl; q.bias = leafb; q.ldw = 1024;
        q.M = BB * LL; q.Ktot = KP_LG; q.nph = 1;
        q.ph_start[0] = 0; q.ph_start[1] = 1 << 20; q.ph_start[2] = 1 << 20;
        q.ph_start[3] = 1 << 20; q.ph_start[4] = 1 << 20;
        tc_gemm2<M_LEAF, false><<<dim3(4, (q.M + MT - 1) / MT), 256, DSMEM>>>(q);
    }
    // up pass: phases syn(2 chunks) + children(64 chunks)
    for (int lvl = 8; lvl >= 0; lvl--) {
        int cnt = 1 << lvl;
        GP q = base;
        q.W = wc; q.bias = compb; q.ldw = 1024;
        q.M = BB * cnt; q.Ktot = KP_COMP; q.nph = 2;
        q.node_base = cnt - 1; q.node_cnt = cnt;
        q.ph_start[0] = 0; q.ph_start[1] = 2; q.ph_start[2] = 1 << 20;
        q.ph_start[3] = 1 << 20; q.ph_start[4] = 1 << 20;
        tc_gemm2<M_UP, true><<<dim3(4, (q.M + MT - 1) / MT), 256, DSMEM>>>(q);
    }
    // grev: phases up-root(32 chunks) + syn(2 chunks)
    {
        GP q = base;
        q.W = wg; q.bias = grevb; q.ldw = 1024;
        q.M = BB; q.Ktot = KP_LG; q.nph = 2;
        q.ph_start[0] = 0; q.ph_start[1] = 32; q.ph_start[2] = 1 << 20;
        q.ph_start[3] = 1 << 20; q.ph_start[4] = 1 << 20;
        tc_gemm2<M_GREV, true><<<dim3(4, 1), 256, DSMEM>>>(q);
    }
    // down pass: phases syn_l(2) + syn_r(2) + down_n(32) + up_n(32)
    for (int lvl = 0; lvl < 9; lvl++) {
        int cnt = 1 << lvl;
        GP q = base;
        q.W = wd; q.bias = decb; q.ldw = 2048;
        q.M = BB * cnt; q.Ktot = KP_DEC; q.nph = 4;
        q.node_base = cnt - 1; q.node_cnt = cnt;
        q.cue = pos;   // M_DOWN uses the cue slot for pos indices of leaf children
        q.ph_start[0] = 0; q.ph_start[1] = 2; q.ph_start[2] = 4;
        q.ph_start[3] = 36; q.ph_start[4] = 1 << 20;
        tc_gemm2<M_DOWN, true><<<dim3(8, (q.M + MT - 1) / MT), 256, DSMEM>>>(q);
    }
    // classifier
    clf_kernel<<<(BB * NSEQ + 7) / 8, 256>>>(clfW, clfb, out);
}

// round 5
// speedup vs baseline: 6.5292x; 1.8700x over previous
#include <cuda_runtime.h>
#include <cuda_fp16.h>
#include <cstdint>
#include <math.h>

#define BB   32
#define NSEQ 1023
#define LL   512
#define HH   1024
#define SHD  50
#define SYNR 128

#define MT     128
#define NTILE  256
#define BK     32
#define STAGES 8

#define A_STR 40                       /* halves per A smem row (80B)  */
#define B_STR 264                      /* halves per B smem row (528B) */
#define AS_BYTES (MT * A_STR * 2)      /* 10240 */
#define BS_BYTES (BK * B_STR * 2)      /* 16896 */
#define STAGE_BYTES (AS_BYTES + BS_BYTES)
#define DSMEM (STAGES * STAGE_BYTES)   /* 217088 */

#define KP_COMP 2112
#define KP_DEC  2176
#define KP_LG   1088

// ---------------- scratch (device globals; no runtime alloc) ----------------
__device__ __half g_up   [(size_t)BB * NSEQ * HH];
__device__ __half g_down [(size_t)BB * NSEQ * HH];
__device__ __half g_wcomp[(size_t)KP_COMP * 1024];
__device__ __half g_wdec [(size_t)KP_DEC  * 2048];
__device__ __half g_wleaf[(size_t)KP_LG   * 1024];
__device__ __half g_wgrev[(size_t)KP_LG   * 1024];
__device__ __half g_syn  [(size_t)SYNR * 64];
__device__ __half g_leafA[(size_t)BB * LL * KP_LG];

// ---------------- helpers ----------------
__device__ __forceinline__ uint32_t smem_u32(const void* p) {
    uint32_t a;
    asm("{ .reg .u64 t; cvta.to.shared.u64 t, %1; cvt.u32.u64 %0, t; }" : "=r"(a) : "l"(p));
    return a;
}
#define CP_ASYNC16(dst, src) \
    asm volatile("cp.async.cg.shared.global [%0], [%1], 16;" :: "r"(dst), "l"(src))
#define CP_COMMIT() asm volatile("cp.async.commit_group;" ::: "memory")
#define CP_WAIT6()  asm volatile("cp.async.wait_group 6;" ::: "memory")

#define LDSM_X4(R, addr) \
    asm volatile("ldmatrix.sync.aligned.m8n8.x4.shared.b16 {%0,%1,%2,%3}, [%4];" \
        : "=r"((R)[0]), "=r"((R)[1]), "=r"((R)[2]), "=r"((R)[3]) : "r"(addr))
#define LDSM_X4T(R, addr) \
    asm volatile("ldmatrix.sync.aligned.m8n8.x4.trans.shared.b16 {%0,%1,%2,%3}, [%4];" \
        : "=r"((R)[0]), "=r"((R)[1]), "=r"((R)[2]), "=r"((R)[3]) : "r"(addr))

#define MMA16816(c, a, b0, b1) \
    asm volatile("mma.sync.aligned.m16n8k16.row.col.f32.f16.f16.f32 " \
        "{%0,%1,%2,%3}, {%4,%5,%6,%7}, {%8,%9}, {%0,%1,%2,%3};" \
        : "+f"((c)[0]), "+f"((c)[1]), "+f"((c)[2]), "+f"((c)[3]) \
        : "r"((a)[0]), "r"((a)[1]), "r"((a)[2]), "r"((a)[3]), "r"(b0), "r"(b1))

enum { M_LEAF = 0, M_UP, M_GREV, M_DOWN };

struct GP {
    const __half* W;      // padded fp16 weights, [Ktot][ldw]
    const float* bias;
    int ldw, M, Ktot, nph, node_base, node_cnt;
    int ph_start[4];
    const int *x, *cue;   // for M_DOWN, cue slot carries pos
    const float* leafW;   // raw fp32, for cue additive rows
};

// ---------------- prep kernels ----------------
__global__ void zero_scratch() {
    const size_t n0 = (size_t)KP_COMP * 1024 / 2, n1 = (size_t)KP_DEC * 2048 / 2,
                 n2 = (size_t)KP_LG * 1024 / 2, n3 = (size_t)SYNR * 64 / 2;
    const size_t total = n0 + n1 + 2 * n2 + n3;
    for (size_t i = (size_t)blockIdx.x * blockDim.x + threadIdx.x; i < total;
         i += (size_t)gridDim.x * blockDim.x) {
        if (i < n0) reinterpret_cast<uint32_t*>(g_wcomp)[i] = 0;
        else if (i < n0 + n1) reinterpret_cast<uint32_t*>(g_wdec)[i - n0] = 0;
        else if (i < n0 + n1 + n2) reinterpret_cast<uint32_t*>(g_wleaf)[i - n0 - n1] = 0;
        else if (i < n0 + n1 + 2 * n2) reinterpret_cast<uint32_t*>(g_wgrev)[i - n0 - n1 - n2] = 0;
        else reinterpret_cast<uint32_t*>(g_syn)[i - n0 - n1 - 2 * n2] = 0;
    }
}

__global__ void copyH(__half* __restrict__ dst, int ldd, int row0,
                      const float* __restrict__ src, int lds, int rows, int cols) {
    size_t total = (size_t)rows * cols;
    for (size_t i = (size_t)blockIdx.x * blockDim.x + threadIdx.x; i < total;
         i += (size_t)gridDim.x * blockDim.x) {
        int r = (int)(i / cols), c = (int)(i % cols);
        dst[(size_t)(row0 + r) * ldd + c] = __float2half_rn(src[(size_t)r * lds + c]);
    }
}

// leaf A rows: [wemb[s] (1024 fp16) | g_syn[pos] (64 fp16)]
__global__ __launch_bounds__(256) void build_leafA(const int* __restrict__ x,
                                                   const int* __restrict__ pos,
                                                   const float* __restrict__ wemb) {
    int row = blockIdx.x * 8 + (threadIdx.x >> 5);
    if (row >= BB * LL) return;
    int lane = threadIdx.x & 31;
    int b = row >> 9, l = row & (LL - 1);
    int w = (LL - 1) + l;
    int s = x[b * NSEQ + w];
    int pr = pos[b * LL + l];
    const float4* src = reinterpret_cast<const float4*>(wemb + (size_t)s * HH);
    __half* dst = g_leafA + (size_t)row * KP_LG;
    #pragma unroll
    for (int i = 0; i < 8; i++) {
        float4 v = src[lane + i * 32];
        __half2 h01 = __floats2half2_rn(v.x, v.y);
        __half2 h23 = __floats2half2_rn(v.z, v.w);
        reinterpret_cast<__half2*>(dst)[(lane + i * 32) * 2]     = h01;
        reinterpret_cast<__half2*>(dst)[(lane + i * 32) * 2 + 1] = h23;
    }
    if (lane < 8)
        reinterpret_cast<uint4*>(dst + 1024)[lane] =
            reinterpret_cast<const uint4*>(g_syn + (size_t)pr * 64)[lane];
}

// ---------------- main fp16 GEMM: cp.async + ldmatrix + mma.m16n8k16 ----------------
template<int MODE, bool DOTANH>
__global__ __launch_bounds__(256) void hgemm(GP p) {
    __shared__ const __half* sAp[4][MT];
    __shared__ __half* sO[MT];
    __shared__ const float* sAdd[MT];
    extern __shared__ __align__(16) char dynraw[];

    const int tid = threadIdx.x;
    const int wid = tid >> 5;
    const int lane = tid & 31;
    const int rbase = blockIdx.y * MT;
    const int nblk = blockIdx.x * NTILE;

    for (int t = tid; t < MT; t += 256) {
        int r = rbase + t;
        const __half *a0 = p.W, *a1 = p.W, *a2 = p.W, *a3 = p.W;
        const float* ad = nullptr;
        __half* o = nullptr;
        if (r < p.M) {
            if (MODE == M_LEAF) {
                int b = r >> 9, l = r & (LL - 1);
                int w = (LL - 1) + l;
                int c = p.cue[b * NSEQ + w];
                a0 = g_leafA + (size_t)r * KP_LG;
                ad = p.leafW + (size_t)(HH + c) * HH;
                o  = g_up + ((size_t)b * NSEQ + w) * HH;
            } else if (MODE == M_UP) {
                int b = r / p.node_cnt, n = p.node_base + r % p.node_cnt;
                a0 = g_syn + (size_t)p.x[b * NSEQ + n] * 64;
                a1 = g_up + ((size_t)b * NSEQ + 2 * n + 1) * HH;   // [up_l;up_r]
                o  = g_up + ((size_t)b * NSEQ + n) * HH;
            } else if (MODE == M_GREV) {
                int b = r;
                a0 = g_up + (size_t)b * NSEQ * HH;
                a1 = g_syn + (size_t)p.x[b * NSEQ] * 64;
                o  = g_down + (size_t)b * NSEQ * HH;
            } else { // M_DOWN
                int b = r / p.node_cnt, n = p.node_base + r % p.node_cnt;
                int cl = 2 * n + 1, cr = 2 * n + 2;
                const int* pp = p.cue;   // pos
                int si_l = (cl >= LL - 1) ? pp[b * LL + cl - (LL - 1)] : p.x[b * NSEQ + cl];
                int si_r = (cr >= LL - 1) ? pp[b * LL + cr - (LL - 1)] : p.x[b * NSEQ + cr];
                a0 = g_syn + (size_t)si_l * 64;
                a1 = g_syn + (size_t)si_r * 64;
                a2 = g_down + ((size_t)b * NSEQ + n) * HH;
                a3 = g_up + ((size_t)b * NSEQ + n) * HH;
                o  = g_down + ((size_t)b * NSEQ + cl) * HH;        // 2048 contiguous
            }
        }
        sAp[0][t] = a0; sAp[1][t] = a1; sAp[2][t] = a2; sAp[3][t] = a3;
        sO[t] = o; sAdd[t] = ad;
    }
    __syncthreads();

    const int nc = p.Ktot / BK;
    const uint32_t dynB = smem_u32(dynraw);

    auto prefetch = [&](int c, int stage) {
        const uint32_t asB = dynB + stage * STAGE_BYTES;
        const uint32_t bsB = asB + AS_BYTES;
        int phidx = 0;
        #pragma unroll
        for (int q = 1; q < 4; q++) if (q < p.nph && c >= p.ph_start[q]) phidx = q;
        const int kloc = (c - p.ph_start[phidx]) * BK;
        // A: 128 rows x 64B = 2 transfers/thread
        #pragma unroll
        for (int i = 0; i < 2; i++) {
            int lin = i * 256 + tid;
            int row = lin >> 2, seg = lin & 3;
            const __half* src = sAp[phidx][row] + kloc + seg * 8;
            CP_ASYNC16(asB + (row * A_STR + seg * 8) * 2, src);
        }
        // B: 32 rows x 512B = 4 transfers/thread
        const __half* wsrc = p.W + (size_t)(c * BK) * p.ldw + nblk;
        #pragma unroll
        for (int i = 0; i < 4; i++) {
            int lin = i * 256 + tid;
            int row = lin >> 5, seg = lin & 31;
            CP_ASYNC16(bsB + (row * B_STR + seg * 8) * 2,
                       wsrc + (size_t)row * p.ldw + seg * 8);
        }
    };

    const int warp_m = wid & 1;
    const int warp_n = wid >> 1;
    const uint32_t aLane = ((warp_m * 64 + (lane & 15)) * A_STR + (lane >> 4) * 8) * 2;
    const uint32_t bLane = ((lane & 15) * B_STR + warp_n * 64 + (lane >> 4) * 8) * 2;

    float cacc[4][8][4];
    #pragma unroll
    for (int i = 0; i < 4; i++)
        #pragma unroll
        for (int j = 0; j < 8; j++)
            #pragma unroll
            for (int e = 0; e < 4; e++) cacc[i][j][e] = 0.f;

    #pragma unroll
    for (int s = 0; s < STAGES - 1; s++) {
        if (s < nc) prefetch(s, s);
        CP_COMMIT();
    }

    for (int c = 0; c < nc; c++) {
        CP_WAIT6();
        __syncthreads();
        const int stage = c & (STAGES - 1);
        const uint32_t asB = dynB + stage * STAGE_BYTES;
        const uint32_t bsB = asB + AS_BYTES;
        #pragma unroll
        for (int kk = 0; kk < 2; kk++) {
            uint32_t af[4][4], bf[4][4];
            #pragma unroll
            for (int mf = 0; mf < 4; mf++)
                LDSM_X4(af[mf], asB + aLane + (mf * 16 * A_STR + kk * 16) * 2);
            #pragma unroll
            for (int nfp = 0; nfp < 4; nfp++)
                LDSM_X4T(bf[nfp], bsB + bLane + (kk * 16 * B_STR + nfp * 16) * 2);
            #pragma unroll
            for (int mf = 0; mf < 4; mf++)
                #pragma unroll
                for (int nfp = 0; nfp < 4; nfp++) {
                    MMA16816(cacc[mf][nfp * 2],     af[mf], bf[nfp][0], bf[nfp][1]);
                    MMA16816(cacc[mf][nfp * 2 + 1], af[mf], bf[nfp][2], bf[nfp][3]);
                }
        }
        int pc = c + STAGES - 1;
        if (pc < nc) prefetch(pc, pc & (STAGES - 1));
        CP_COMMIT();
    }

    // epilogue: fp32 bias (+cue row) (+tanh), half2 stores
    {
        const int g = lane >> 2, t = lane & 3;
        #pragma unroll
        for (int mf = 0; mf < 4; mf++) {
            const int tr1 = warp_m * 64 + mf * 16 + g;
            const int tr2 = tr1 + 8;
            __half* o1 = sO[tr1];
            __half* o2 = sO[tr2];
            const float* ad1 = sAdd[tr1];
            const float* ad2 = sAdd[tr2];
            #pragma unroll
            for (int nf = 0; nf < 8; nf++) {
                const int col0 = nblk + warp_n * 64 + nf * 8 + t * 2;
                const float b0 = p.bias[col0], b1 = p.bias[col0 + 1];
                const float* cc = cacc[mf][nf];
                if (o1) {
                    float v0 = cc[0] + b0, v1 = cc[1] + b1;
                    if (MODE == M_LEAF && ad1) { v0 += ad1[col0]; v1 += ad1[col0 + 1]; }
                    if (DOTANH) { v0 = tanhf(v0); v1 = tanhf(v1); }
                    *reinterpret_cast<__half2*>(o1 + col0) = __floats2half2_rn(v0, v1);
                }
                if (o2) {
                    float v0 = cc[2] + b0, v1 = cc[3] + b1;
                    if (MODE == M_LEAF && ad2) { v0 += ad2[col0]; v1 += ad2[col0 + 1]; }
                    if (DOTANH) { v0 = tanhf(v0); v1 = tanhf(v1); }
                    *reinterpret_cast<__half2*>(o2 + col0) = __floats2half2_rn(v0, v1);
                }
            }
        }
    }
}

// ---------------- classifier ----------------
__global__ __launch_bounds__(256) void clf_kernel(const float* __restrict__ clfW,
                                                  const float* __restrict__ clfb,
                                                  float* __restrict__ out) {
    int row = blockIdx.x * 8 + (threadIdx.x >> 5);
    if (row >= BB * NSEQ) return;
    int lane = threadIdx.x & 31;
    const __half2* dn = reinterpret_cast<const __half2*>(g_down + (size_t)row * HH);
    const __half2* up = reinterpret_cast<const __half2*>(g_up   + (size_t)row * HH);
    float s0 = 0.f, s1 = 0.f, s2 = 0.f;
    for (int i = lane; i < 512; i += 32) {
        float2 d = __half22float2(dn[i]);
        float2 u = __half22float2(up[i]);
        int k = 2 * i;
        const float* w  = clfW + (size_t)k * 3;
        const float* w2 = clfW + (size_t)(k + HH) * 3;
        s0 += d.x * w[0] + d.y * w[3] + u.x * w2[0] + u.y * w2[3];
        s1 += d.x * w[1] + d.y * w[4] + u.x * w2[1] + u.y * w2[4];
        s2 += d.x * w[2] + d.y * w[5] + u.x * w2[2] + u.y * w2[5];
    }
    #pragma unroll
    for (int o = 16; o > 0; o >>= 1) {
        s0 += __shfl_xor_sync(0xFFFFFFFFu, s0, o);
        s1 += __shfl_xor_sync(0xFFFFFFFFu, s1, o);
        s2 += __shfl_xor_sync(0xFFFFFFFFu, s2, o);
    }
    if (lane == 0) {
        out[(size_t)row * 3 + 0] = tanhf(s0 + clfb[0]);
        out[(size_t)row * 3 + 1] = tanhf(s1 + clfb[1]);
        out[(size_t)row * 3 + 2] = tanhf(s2 + clfb[2]);
    }
}

// ---------------- host ----------------
extern "C" void kernel_launch(void* const* d_in, const int* in_sizes, int n_in,
                              void* d_out, int out_size) {
    (void)in_sizes; (void)n_in; (void)out_size;
    const int*   x     = (const int*)  d_in[0];
    const int*   cue   = (const int*)  d_in[2];
    const int*   pos   = (const int*)  d_in[4];
    const float* wemb  = (const float*)d_in[6];
    const float* syn   = (const float*)d_in[7];
    const float* leafW = (const float*)d_in[8];
    const float* leafb = (const float*)d_in[9];
    const float* compW = (const float*)d_in[10];
    const float* compb = (const float*)d_in[11];
    const float* grevW = (const float*)d_in[12];
    const float* grevb = (const float*)d_in[13];
    const float* decW  = (const float*)d_in[14];
    const float* decb  = (const float*)d_in[15];
    const float* clfW  = (const float*)d_in[16];
    const float* clfb  = (const float*)d_in[17];
    float* out = (float*)d_out;

    __half *wc, *wd, *wl, *wg, *sy;
    cudaGetSymbolAddress((void**)&wc, g_wcomp);
    cudaGetSymbolAddress((void**)&wd, g_wdec);
    cudaGetSymbolAddress((void**)&wl, g_wleaf);
    cudaGetSymbolAddress((void**)&wg, g_wgrev);
    cudaGetSymbolAddress((void**)&sy, g_syn);

    cudaFuncSetAttribute(hgemm<M_LEAF, false>, cudaFuncAttributeMaxDynamicSharedMemorySize, DSMEM);
    cudaFuncSetAttribute(hgemm<M_UP,   true>,  cudaFuncAttributeMaxDynamicSharedMemorySize, DSMEM);
    cudaFuncSetAttribute(hgemm<M_GREV, true>,  cudaFuncAttributeMaxDynamicSharedMemorySize, DSMEM);
    cudaFuncSetAttribute(hgemm<M_DOWN, true>,  cudaFuncAttributeMaxDynamicSharedMemorySize, DSMEM);

    // prep
    zero_scratch<<<2048, 256>>>();
    auto cp = [&](__half* dst, int ldd, int row0, const float* src, int lds, int rows, int cols) {
        size_t n = (size_t)rows * cols;
        int blocks = (int)((n + 255) / 256);
        if (blocks > 4096) blocks = 4096;
        copyH<<<blocks, 256>>>(dst, ldd, row0, src, lds, rows, cols);
    };
    cp(sy, 64, 0, syn, SHD, SYNR, SHD);
    cp(wc, 1024, 0,  compW, 1024, 50, 1024);
    cp(wc, 1024, 64, compW + (size_t)50 * 1024, 1024, 2048, 1024);
    cp(wd, 2048, 0,   decW, 2048, 50, 2048);
    cp(wd, 2048, 64,  decW + (size_t)50 * 2048, 2048, 50, 2048);
    cp(wd, 2048, 128, decW + (size_t)100 * 2048, 2048, 2048, 2048);
    cp(wl, 1024, 0,    leafW, 1024, 1024, 1024);
    cp(wl, 1024, 1024, leafW + (size_t)1027 * 1024, 1024, 50, 1024);
    cp(wg, 1024, 0,    grevW, 1024, 1024, 1024);
    cp(wg, 1024, 1024, grevW + (size_t)1024 * 1024, 1024, 50, 1024);
    build_leafA<<<(BB * LL + 7) / 8, 256>>>(x, pos, wemb);

    GP base{};
    base.x = x; base.cue = cue; base.leafW = leafW;
    base.node_base = 0; base.node_cnt = 1;

    // leaf (K=1088, 1 phase)
    {
        GP q = base;
        q.W = wl; q.bias = leafb; q.ldw = 1024;
        q.M = BB * LL; q.Ktot = KP_LG; q.nph = 1;
        q.ph_start[0] = 0; q.ph_start[1] = 1 << 20; q.ph_start[2] = 1 << 20; q.ph_start[3] = 1 << 20;
        hgemm<M_LEAF, false><<<dim3(4, (q.M + MT - 1) / MT), 256, DSMEM>>>(q);
    }
    // up pass
    for (int lvl = 8; lvl >= 0; lvl--) {
        int cnt = 1 << lvl;
        GP q = base;
        q.W = wc; q.bias = compb; q.ldw = 1024;
        q.M = BB * cnt; q.Ktot = KP_COMP; q.nph = 2;
        q.node_base = cnt - 1; q.node_cnt = cnt;
        q.ph_start[0] = 0; q.ph_start[1] = 2; q.ph_start[2] = 1 << 20; q.ph_start[3] = 1 << 20;
        hgemm<M_UP, true><<<dim3(4, (q.M + MT - 1) / MT), 256, DSMEM>>>(q);
    }
    // grev
    {
        GP q = base;
        q.W = wg; q.bias = grevb; q.ldw = 1024;
        q.M = BB; q.Ktot = KP_LG; q.nph = 2;
        q.ph_start[0] = 0; q.ph_start[1] = 32; q.ph_start[2] = 1 << 20; q.ph_start[3] = 1 << 20;
        hgemm<M_GREV, true><<<dim3(4, 1), 256, DSMEM>>>(q);
    }
    // down pass
    for (int lvl = 0; lvl < 9; lvl++) {
        int cnt = 1 << lvl;
        GP q = base;
        q.W = wd; q.bias = decb; q.ldw = 2048;
        q.M = BB * cnt; q.Ktot = KP_DEC; q.nph = 4;
        q.node_base = cnt - 1; q.node_cnt = cnt;
        q.cue = pos;                     // pos indices for leaf children
        q.ph_start[0] = 0; q.ph_start[1] = 2; q.ph_start[2] = 4; q.ph_start[3] = 36;
        hgemm<M_DOWN, true><<<dim3(8, (q.M + MT - 1) / MT), 256, DSMEM>>>(q);
    }
    clf_kernel<<<(BB * NSEQ + 7) / 8, 256>>>(clfW, clfb, out);
}